// round 6
// baseline (speedup 1.0000x reference)
#include <cuda_runtime.h>
#include <math.h>
#include <string.h>

#define S_LEN 512
#define B_SZ  256
#define E_DIM 128
#define H_DIM 256

static __device__ float g_xproj[(size_t)S_LEN * B_SZ * H_DIM];

typedef unsigned long long ull;

__device__ __forceinline__ void ffma2(ull& d, ull a, ull b) {
    asm("fma.rn.f32x2 %0, %1, %2, %0;" : "+l"(d) : "l"(a), "l"(b));
}
__device__ __forceinline__ ull dup2(float w) {
    ull p;
    asm("mov.b64 %0, {%1, %1};" : "=l"(p) : "f"(w));
    return p;
}
__device__ __forceinline__ float2 as_f2(ull v) {
    float2 f; memcpy(&f, &v, 8); return f;
}

// ---------------------------------------------------------------------------
// Kernel 1: fused gather + input projection, 128x128-tile GEMM.
// grid = (1024, 2): blockIdx.x = m-tile, blockIdx.y = n-half.
// 256 threads, each computes an 8m x 8n fragment. As/Bs k-major in smem.
// ---------------------------------------------------------------------------
__global__ void __launch_bounds__(256, 1) xproj_kernel(
    const int* __restrict__ X, const float* __restrict__ emb,
    const float* __restrict__ W_ih, const float* __restrict__ b_ih,
    const float* __restrict__ b_hh)
{
    extern __shared__ __align__(16) float xsm[];
    float* As = xsm;                  // [k][m] 128x128
    float* Bs = xsm + 128 * 128;      // [k][n] 128x128
    int*   ids = (int*)(Bs + 128 * 128);

    const int t  = threadIdx.x;
    const int m0 = blockIdx.x * 128;
    const int n0 = blockIdx.y * 128;

    if (t < 128) ids[t] = X[m0 + t];
    __syncthreads();

    // Stage A (gathered emb rows) and B (W_ih rows), both transposed to k-major.
    // 4096 float4 each, 16 per thread; STS addresses lane-consecutive in m/n.
#pragma unroll
    for (int it = 0; it < 16; it++) {
        int idx = t + 256 * it;
        int r = idx & 127, q = idx >> 7;           // q: 0..31
        float4 fa = ((const float4*)(emb + (size_t)ids[r] * E_DIM))[q];
        As[(4 * q + 0) * 128 + r] = fa.x;
        As[(4 * q + 1) * 128 + r] = fa.y;
        As[(4 * q + 2) * 128 + r] = fa.z;
        As[(4 * q + 3) * 128 + r] = fa.w;
        float4 fb = ((const float4*)(W_ih + (size_t)(n0 + r) * E_DIM))[q];
        Bs[(4 * q + 0) * 128 + r] = fb.x;
        Bs[(4 * q + 1) * 128 + r] = fb.y;
        Bs[(4 * q + 2) * 128 + r] = fb.z;
        Bs[(4 * q + 3) * 128 + r] = fb.w;
    }
    __syncthreads();

    const int tx = t & 15, ty = t >> 4;   // n-frag = tx*8, m-frag = ty*8

    ull acc[32];                          // acc[m*4+p]: m 0..7, n-pair p 0..3
#pragma unroll
    for (int i = 0; i < 32; i++) acc[i] = 0ULL;

#pragma unroll 4
    for (int k = 0; k < 128; k++) {
        float4 a0 = *(const float4*)(As + k * 128 + ty * 8);
        float4 a1 = *(const float4*)(As + k * 128 + ty * 8 + 4);
        ulonglong2 bl = *(const ulonglong2*)(Bs + k * 128 + tx * 8);
        ulonglong2 bh = *(const ulonglong2*)(Bs + k * 128 + tx * 8 + 4);
        float am[8] = {a0.x, a0.y, a0.z, a0.w, a1.x, a1.y, a1.z, a1.w};
#pragma unroll
        for (int m = 0; m < 8; m++) {
            ull ad = dup2(am[m]);
            ffma2(acc[m * 4 + 0], bl.x, ad);
            ffma2(acc[m * 4 + 1], bl.y, ad);
            ffma2(acc[m * 4 + 2], bh.x, ad);
            ffma2(acc[m * 4 + 3], bh.y, ad);
        }
    }

    float bias[8];
#pragma unroll
    for (int j = 0; j < 8; j++) {
        int n = n0 + tx * 8 + j;
        bias[j] = b_ih[n] + b_hh[n];
    }
#pragma unroll
    for (int m = 0; m < 8; m++) {
        float o[8];
#pragma unroll
        for (int p = 0; p < 4; p++) {
            float2 f = as_f2(acc[m * 4 + p]);
            o[2 * p] = f.x + bias[2 * p];
            o[2 * p + 1] = f.y + bias[2 * p + 1];
        }
        float* dst = g_xproj + (size_t)(m0 + ty * 8 + m) * H_DIM + n0 + tx * 8;
        *(float4*)(dst)     = make_float4(o[0], o[1], o[2], o[3]);
        *(float4*)(dst + 4) = make_float4(o[4], o[5], o[6], o[7]);
    }
}

// ---------------------------------------------------------------------------
// Kernel 2: 512-step recurrence + fused log_softmax. 512 threads, 2 rows/CTA.
// Thread t: io = t>>2 (0..127), jg = t&3 (j-slice [64jg,64jg+64)).
// Computes partials for outputs {io, io+128}, rows A,B over its slice.
// W[io][slice] in 64 regs; W[io+128][slice] in smem (lane-distinct).
// j-reduction via 2 shfl.bfly rounds within the 4-lane jg group; lane jg
// finalizes combo (row=jg>>1, out=io+128*(jg&1)): xp add + tanh + 4 replica
// stores. h kept in 4 bank-staggered replicas (stride 260 floats), ping-pong
// buffered -> ONE __syncthreads per step.
// ---------------------------------------------------------------------------
__global__ void __launch_bounds__(512, 1) rnn_kernel(
    const float* __restrict__ W_hh, float* __restrict__ out)
{
    extern __shared__ __align__(16) float sm[];
    ulonglong2* Wsm = (ulonglong2*)sm;   // [16][512] ulonglong2 = 128 KB
    float* h   = sm + 32768;             // [2 buf][2 row][4 rep * 260] = 4160 floats
    float* red = h + 4160;               // [512]

    const int t  = threadIdx.x;
    const int io = t >> 2;
    const int jg = t & 3;
    const int b0 = blockIdx.x * 2;

    // W row io+128, slice [64jg, 64jg+64) -> smem
    {
        const ulonglong2* w1 = (const ulonglong2*)(W_hh + (size_t)(io + 128) * H_DIM + 64 * jg);
#pragma unroll
        for (int q = 0; q < 16; q++) Wsm[q * 512 + t] = w1[q];
    }
    // W row io, same slice -> 64 registers
    ull Wp[32];
    {
        const ulonglong2* w0 = (const ulonglong2*)(W_hh + (size_t)io * H_DIM + 64 * jg);
#pragma unroll
        for (int q = 0; q < 16; q++) {
            ulonglong2 v = w0[q];
            Wp[2 * q] = v.x; Wp[2 * q + 1] = v.y;
        }
    }

    for (int i = t; i < 4160; i += 512) h[i] = 0.0f;
    __syncthreads();

    // Finalize combo for this thread
    const int frow = jg >> 1;
    const int fout = io + 128 * (jg & 1);
    const float* xpp = g_xproj + (size_t)(b0 + frow) * H_DIM + fout;
    float xpv = xpp[0];

    for (int s = 0; s < S_LEN; s++) {
        float xnext = 0.0f;
        if (s + 1 < S_LEN) xnext = xpp[(size_t)(s + 1) * (B_SZ * H_DIM)];

        // Read pointers: buffer s&1, replica jg (stagger 260 floats),
        // slice offset 64*jg -> combined float offset jg*324 (16B aligned).
        const float* hb = h + (s & 1) * 2080;
        const ulonglong2* hA = (const ulonglong2*)(hb + jg * 324);
        const ulonglong2* hB = (const ulonglong2*)(hb + 1040 + jg * 324);

        ull aA0 = 0ULL, aA1 = 0ULL, aB0 = 0ULL, aB1 = 0ULL;
#pragma unroll
        for (int q = 0; q < 16; q++) {
            ulonglong2 ha = hA[q];              // broadcast, conflict-free
            ulonglong2 hbq = hB[q];             // broadcast, conflict-free
            ulonglong2 ws = Wsm[q * 512 + t];   // distinct, conflict-free
            ffma2(aA0, Wp[2 * q], ha.x);  ffma2(aA0, Wp[2 * q + 1], ha.y);
            ffma2(aA1, ws.x,      ha.x);  ffma2(aA1, ws.y,      ha.y);
            ffma2(aB0, Wp[2 * q], hbq.x); ffma2(aB0, Wp[2 * q + 1], hbq.y);
            ffma2(aB1, ws.x,      hbq.x); ffma2(aB1, ws.y,      hbq.y);
        }

        float2 f;
        f = as_f2(aA0); float sA0 = f.x + f.y;
        f = as_f2(aA1); float sA1 = f.x + f.y;
        f = as_f2(aB0); float sB0 = f.x + f.y;
        f = as_f2(aB1); float sB1 = f.x + f.y;

        // reduce over jg (lanes xor 1, xor 2)
        sA0 += __shfl_xor_sync(0xffffffffu, sA0, 1);
        sA0 += __shfl_xor_sync(0xffffffffu, sA0, 2);
        sA1 += __shfl_xor_sync(0xffffffffu, sA1, 1);
        sA1 += __shfl_xor_sync(0xffffffffu, sA1, 2);
        sB0 += __shfl_xor_sync(0xffffffffu, sB0, 1);
        sB0 += __shfl_xor_sync(0xffffffffu, sB0, 2);
        sB1 += __shfl_xor_sync(0xffffffffu, sB1, 1);
        sB1 += __shfl_xor_sync(0xffffffffu, sB1, 2);

        float xsel = (jg & 2) ? ((jg & 1) ? sB1 : sB0)
                              : ((jg & 1) ? sA1 : sA0);
        float hn = tanhf(xsel + xpv);

        float* wdst = h + ((s + 1) & 1) * 2080 + frow * 1040 + fout;
        wdst[0]       = hn;
        wdst[260]     = hn;
        wdst[520]     = hn;
        wdst[780]     = hn;
        __syncthreads();

        xpv = xnext;
    }

    // Final h in buffer 0, replica 0. Softmax: row fr = t>>8, elem fo = t&255.
    const int fr = t >> 8, fo = t & 255;
    float x = h[fr * 1040 + fo];

    red[t] = x;
    __syncthreads();
    for (int off = 128; off > 0; off >>= 1) {
        if (fo < off) red[t] = fmaxf(red[t], red[t + off]);
        __syncthreads();
    }
    float mx = red[fr * 256];
    __syncthreads();

    red[t] = expf(x - mx);
    __syncthreads();
    for (int off = 128; off > 0; off >>= 1) {
        if (fo < off) red[t] = red[t] + red[t + off];
        __syncthreads();
    }
    float lse = logf(red[fr * 256]);

    out[(size_t)(b0 + fr) * H_DIM + fo] = x - mx - lse;
}

extern "C" void kernel_launch(void* const* d_in, const int* in_sizes, int n_in,
                              void* d_out, int out_size)
{
    const int*   X    = (const int*)d_in[0];
    const float* emb  = (const float*)d_in[1];
    const float* W_ih = (const float*)d_in[2];
    const float* W_hh = (const float*)d_in[3];
    const float* b_ih = (const float*)d_in[4];
    const float* b_hh = (const float*)d_in[5];
    float* out = (float*)d_out;

    const int smem_xproj = (128 * 128 * 2) * 4 + 128 * 4;            // 131584 B
    const int smem_rnn   = 32768 * 4 + (4160 + 512) * 4;             // 149760 B
    cudaFuncSetAttribute(xproj_kernel, cudaFuncAttributeMaxDynamicSharedMemorySize, smem_xproj);
    cudaFuncSetAttribute(rnn_kernel,   cudaFuncAttributeMaxDynamicSharedMemorySize, smem_rnn);

    dim3 xgrid((S_LEN * B_SZ) / 128, 2);
    xproj_kernel<<<xgrid, 256, smem_xproj>>>(X, emb, W_ih, b_ih, b_hh);
    rnn_kernel<<<B_SZ / 2, 512, smem_rnn>>>(W_hh, out);
}

// round 8
// speedup vs baseline: 1.2755x; 1.2755x over previous
#include <cuda_runtime.h>
#include <math.h>
#include <string.h>

#define S_LEN 512
#define B_SZ  256
#define E_DIM 128
#define H_DIM 256

static __device__ float g_xproj[(size_t)S_LEN * B_SZ * H_DIM];

typedef unsigned long long ull;

__device__ __forceinline__ void ffma2(ull& d, ull a, ull b) {
    asm("fma.rn.f32x2 %0, %1, %2, %0;" : "+l"(d) : "l"(a), "l"(b));
}
__device__ __forceinline__ ull dup2(float w) {
    ull p;
    asm("mov.b64 %0, {%1, %1};" : "=l"(p) : "f"(w));
    return p;
}
__device__ __forceinline__ float2 as_f2(ull v) {
    float2 f; memcpy(&f, &v, 8); return f;
}

// ---------------------------------------------------------------------------
// Kernel 1: fused gather + input projection, 128x128-tile GEMM.
// grid = (1024, 2): blockIdx.x = m-tile, blockIdx.y = n-half.
// 256 threads, each computes an 8m x 8n fragment. As/Bs k-major in smem.
// Per k per SMSP: 10 LDS-wavefronts vs 128 FMA-cycles -> FMA-bound.
// ---------------------------------------------------------------------------
__global__ void __launch_bounds__(256, 1) xproj_kernel(
    const int* __restrict__ X, const float* __restrict__ emb,
    const float* __restrict__ W_ih, const float* __restrict__ b_ih,
    const float* __restrict__ b_hh)
{
    extern __shared__ __align__(16) float xsm[];
    float* As = xsm;                  // [k][m] 128x128
    float* Bs = xsm + 128 * 128;      // [k][n] 128x128
    int*   ids = (int*)(Bs + 128 * 128);

    const int t  = threadIdx.x;
    const int m0 = blockIdx.x * 128;
    const int n0 = blockIdx.y * 128;

    if (t < 128) ids[t] = X[m0 + t];
    __syncthreads();

    // Stage A (gathered emb rows) and B (W_ih rows), transposed to k-major.
#pragma unroll
    for (int it = 0; it < 16; it++) {
        int idx = t + 256 * it;
        int rr = idx & 127, q = idx >> 7;          // q: 0..31
        float4 fa = ((const float4*)(emb + (size_t)ids[rr] * E_DIM))[q];
        As[(4 * q + 0) * 128 + rr] = fa.x;
        As[(4 * q + 1) * 128 + rr] = fa.y;
        As[(4 * q + 2) * 128 + rr] = fa.z;
        As[(4 * q + 3) * 128 + rr] = fa.w;
        float4 fb = ((const float4*)(W_ih + (size_t)(n0 + rr) * E_DIM))[q];
        Bs[(4 * q + 0) * 128 + rr] = fb.x;
        Bs[(4 * q + 1) * 128 + rr] = fb.y;
        Bs[(4 * q + 2) * 128 + rr] = fb.z;
        Bs[(4 * q + 3) * 128 + rr] = fb.w;
    }
    __syncthreads();

    const int tx = t & 15, ty = t >> 4;   // n-frag = tx*8, m-frag = ty*8

    ull acc[32];                          // acc[m*4+p]
#pragma unroll
    for (int i = 0; i < 32; i++) acc[i] = 0ULL;

#pragma unroll 4
    for (int k = 0; k < 128; k++) {
        float4 a0 = *(const float4*)(As + k * 128 + ty * 8);
        float4 a1 = *(const float4*)(As + k * 128 + ty * 8 + 4);
        ulonglong2 bl = *(const ulonglong2*)(Bs + k * 128 + tx * 8);
        ulonglong2 bh = *(const ulonglong2*)(Bs + k * 128 + tx * 8 + 4);
        float am[8] = {a0.x, a0.y, a0.z, a0.w, a1.x, a1.y, a1.z, a1.w};
#pragma unroll
        for (int m = 0; m < 8; m++) {
            ull ad = dup2(am[m]);
            ffma2(acc[m * 4 + 0], bl.x, ad);
            ffma2(acc[m * 4 + 1], bl.y, ad);
            ffma2(acc[m * 4 + 2], bh.x, ad);
            ffma2(acc[m * 4 + 3], bh.y, ad);
        }
    }

    float bias[8];
#pragma unroll
    for (int j = 0; j < 8; j++) {
        int n = n0 + tx * 8 + j;
        bias[j] = b_ih[n] + b_hh[n];
    }
#pragma unroll
    for (int m = 0; m < 8; m++) {
        float o[8];
#pragma unroll
        for (int p = 0; p < 4; p++) {
            float2 f = as_f2(acc[m * 4 + p]);
            o[2 * p]     = f.x + bias[2 * p];
            o[2 * p + 1] = f.y + bias[2 * p + 1];
        }
        float* dst = g_xproj + (size_t)(m0 + ty * 8 + m) * H_DIM + n0 + tx * 8;
        *(float4*)(dst)     = make_float4(o[0], o[1], o[2], o[3]);
        *(float4*)(dst + 4) = make_float4(o[4], o[5], o[6], o[7]);
    }
}

// ---------------------------------------------------------------------------
// Kernel 2: 512-step recurrence + fused log_softmax (R5 proven version).
// 512 threads, 2 batch rows per CTA (grid 128).
// Compute role: thread (io = t&127, jg = t>>7) handles outputs {io, io+128}
//   over j in [64jg, 64jg+64) for both rows: W[io][slice] in 64 regs,
//   W[io+128][slice] in smem (lane-distinct ulonglong2, conflict-free).
// Finalize role: thread (r = t>>8, o = t&255) sums 4 partials + xp, tanh,
//   writes h in place. Two barriers per step.
// ---------------------------------------------------------------------------
__global__ void __launch_bounds__(512, 1) rnn_kernel(
    const float* __restrict__ W_hh, float* __restrict__ out)
{
    extern __shared__ __align__(16) float sm[];
    ulonglong2* Wsm = (ulonglong2*)sm;     // [16][512] ulonglong2 = 128 KB
    float* h    = sm + 32768;              // [2][256]
    float* part = h + 512;                 // [2][256][4]
    float* red  = part + 2048;             // [2][256]

    const int t  = threadIdx.x;
    const int io = t & 127;
    const int jg = t >> 7;                 // 0..3
    const int b0 = blockIdx.x * 2;

    // W row io -> regs, row io+128 -> smem; j slice [64jg, 64jg+64)
    {
        const ulonglong2* w1 = (const ulonglong2*)(W_hh + (size_t)(io + 128) * H_DIM + 64 * jg);
#pragma unroll
        for (int q = 0; q < 16; q++) Wsm[q * 512 + t] = w1[q];
    }
    ull Wp[32];
    {
        const ulonglong2* w0 = (const ulonglong2*)(W_hh + (size_t)io * H_DIM + 64 * jg);
#pragma unroll
        for (int q = 0; q < 16; q++) {
            ulonglong2 v = w0[q];
            Wp[2 * q] = v.x; Wp[2 * q + 1] = v.y;
        }
    }

    h[t] = 0.0f;                           // t<512 covers both rows
    __syncthreads();

    // finalize mapping
    const int fr = t >> 8, fo = t & 255;
    const float* xpp = g_xproj + (size_t)(b0 + fr) * H_DIM + fo;
    float xpv = xpp[0];

    const ulonglong2* hAq = (const ulonglong2*)(h + 64 * jg);
    const ulonglong2* hBq = (const ulonglong2*)(h + 256 + 64 * jg);

    for (int s = 0; s < S_LEN; s++) {
        float xnext = 0.0f;
        if (s + 1 < S_LEN) xnext = xpp[(size_t)(s + 1) * (B_SZ * H_DIM)];

        ull aA0 = 0ULL, aA1 = 0ULL, aB0 = 0ULL, aB1 = 0ULL;
#pragma unroll
        for (int q = 0; q < 16; q++) {
            ulonglong2 ha = hAq[q];             // broadcast
            ulonglong2 hb = hBq[q];             // broadcast
            ulonglong2 ws = Wsm[q * 512 + t];   // distinct, conflict-free
            ffma2(aA0, Wp[2 * q], ha.x); ffma2(aA0, Wp[2 * q + 1], ha.y);
            ffma2(aA1, ws.x,      ha.x); ffma2(aA1, ws.y,      ha.y);
            ffma2(aB0, Wp[2 * q], hb.x); ffma2(aB0, Wp[2 * q + 1], hb.y);
            ffma2(aB1, ws.x,      hb.x); ffma2(aB1, ws.y,      hb.y);
        }
        {
            float2 f0 = as_f2(aA0), f1 = as_f2(aA1);
            float2 f2 = as_f2(aB0), f3 = as_f2(aB1);
            part[(0 * 256 + io      ) * 4 + jg] = f0.x + f0.y;
            part[(0 * 256 + io + 128) * 4 + jg] = f1.x + f1.y;
            part[(1 * 256 + io      ) * 4 + jg] = f2.x + f2.y;
            part[(1 * 256 + io + 128) * 4 + jg] = f3.x + f3.y;
        }
        __syncthreads();   // partials visible; h reads done

        float4 p4 = *(const float4*)(part + t * 4);
        float hn = tanhf(((p4.x + p4.y) + (p4.z + p4.w)) + xpv);
        h[t] = hn;         // in-place update safe: h no longer read this step
        __syncthreads();   // new h visible

        xpv = xnext;
    }

    // Fused log_softmax, both rows in parallel (row = fr, element = fo).
    float x = h[t];

    red[t] = x;
    __syncthreads();
    for (int off = 128; off > 0; off >>= 1) {
        if (fo < off) red[t] = fmaxf(red[t], red[t + off]);
        __syncthreads();
    }
    float mx = red[fr * 256];
    __syncthreads();

    red[t] = expf(x - mx);
    __syncthreads();
    for (int off = 128; off > 0; off >>= 1) {
        if (fo < off) red[t] = red[t] + red[t + off];
        __syncthreads();
    }
    float lse = logf(red[fr * 256]);

    out[(size_t)(b0 + fr) * H_DIM + fo] = x - mx - lse;
}

extern "C" void kernel_launch(void* const* d_in, const int* in_sizes, int n_in,
                              void* d_out, int out_size)
{
    const int*   X    = (const int*)d_in[0];
    const float* emb  = (const float*)d_in[1];
    const float* W_ih = (const float*)d_in[2];
    const float* W_hh = (const float*)d_in[3];
    const float* b_ih = (const float*)d_in[4];
    const float* b_hh = (const float*)d_in[5];
    float* out = (float*)d_out;

    const int smem_xproj = (128 * 128 * 2) * 4 + 128 * 4;     // 131584 B
    const int smem_rnn   = (32768 + 512 + 2048 + 512) * 4;    // 143360 B
    cudaFuncSetAttribute(xproj_kernel, cudaFuncAttributeMaxDynamicSharedMemorySize, smem_xproj);
    cudaFuncSetAttribute(rnn_kernel,   cudaFuncAttributeMaxDynamicSharedMemorySize, smem_rnn);

    dim3 xgrid((S_LEN * B_SZ) / 128, 2);
    xproj_kernel<<<xgrid, 256, smem_xproj>>>(X, emb, W_ih, b_ih, b_hh);
    rnn_kernel<<<B_SZ / 2, 512, smem_rnn>>>(W_hh, out);
}

// round 12
// speedup vs baseline: 1.3334x; 1.0453x over previous
#include <cuda_runtime.h>
#include <math.h>
#include <string.h>

#define S_LEN 512
#define B_SZ  256
#define E_DIM 128
#define H_DIM 256

static __device__ float g_xproj[(size_t)S_LEN * B_SZ * H_DIM];

typedef unsigned long long ull;

__device__ __forceinline__ void ffma2(ull& d, ull a, ull b) {
    asm("fma.rn.f32x2 %0, %1, %2, %0;" : "+l"(d) : "l"(a), "l"(b));
}
__device__ __forceinline__ ull dup2(float w) {
    ull p;
    asm("mov.b64 %0, {%1, %1};" : "=l"(p) : "f"(w));
    return p;
}
__device__ __forceinline__ float2 as_f2(ull v) {
    float2 f; memcpy(&f, &v, 8); return f;
}

// ---------------------------------------------------------------------------
// Kernel 1: fused gather + input projection, 128x128-tile GEMM (proven R8).
// grid = (1024, 2). 256 threads, 8x8 fragment each, As/Bs k-major in smem.
// ---------------------------------------------------------------------------
__global__ void __launch_bounds__(256, 1) xproj_kernel(
    const int* __restrict__ X, const float* __restrict__ emb,
    const float* __restrict__ W_ih, const float* __restrict__ b_ih,
    const float* __restrict__ b_hh)
{
    extern __shared__ __align__(16) float xsm[];
    float* As = xsm;                  // [k][m] 128x128
    float* Bs = xsm + 128 * 128;      // [k][n] 128x128
    int*   ids = (int*)(Bs + 128 * 128);

    const int t  = threadIdx.x;
    const int m0 = blockIdx.x * 128;
    const int n0 = blockIdx.y * 128;

    if (t < 128) ids[t] = X[m0 + t];
    __syncthreads();

#pragma unroll
    for (int it = 0; it < 16; it++) {
        int idx = t + 256 * it;
        int rr = idx & 127, q = idx >> 7;
        float4 fa = ((const float4*)(emb + (size_t)ids[rr] * E_DIM))[q];
        As[(4 * q + 0) * 128 + rr] = fa.x;
        As[(4 * q + 1) * 128 + rr] = fa.y;
        As[(4 * q + 2) * 128 + rr] = fa.z;
        As[(4 * q + 3) * 128 + rr] = fa.w;
        float4 fb = ((const float4*)(W_ih + (size_t)(n0 + rr) * E_DIM))[q];
        Bs[(4 * q + 0) * 128 + rr] = fb.x;
        Bs[(4 * q + 1) * 128 + rr] = fb.y;
        Bs[(4 * q + 2) * 128 + rr] = fb.z;
        Bs[(4 * q + 3) * 128 + rr] = fb.w;
    }
    __syncthreads();

    const int tx = t & 15, ty = t >> 4;

    ull acc[32];
#pragma unroll
    for (int i = 0; i < 32; i++) acc[i] = 0ULL;

#pragma unroll 4
    for (int k = 0; k < 128; k++) {
        float4 a0 = *(const float4*)(As + k * 128 + ty * 8);
        float4 a1 = *(const float4*)(As + k * 128 + ty * 8 + 4);
        ulonglong2 bl = *(const ulonglong2*)(Bs + k * 128 + tx * 8);
        ulonglong2 bh = *(const ulonglong2*)(Bs + k * 128 + tx * 8 + 4);
        float am[8] = {a0.x, a0.y, a0.z, a0.w, a1.x, a1.y, a1.z, a1.w};
#pragma unroll
        for (int m = 0; m < 8; m++) {
            ull ad = dup2(am[m]);
            ffma2(acc[m * 4 + 0], bl.x, ad);
            ffma2(acc[m * 4 + 1], bl.y, ad);
            ffma2(acc[m * 4 + 2], bh.x, ad);
            ffma2(acc[m * 4 + 3], bh.y, ad);
        }
    }

    float bias[8];
#pragma unroll
    for (int j = 0; j < 8; j++) {
        int n = n0 + tx * 8 + j;
        bias[j] = b_ih[n] + b_hh[n];
    }
#pragma unroll
    for (int m = 0; m < 8; m++) {
        float o[8];
#pragma unroll
        for (int p = 0; p < 4; p++) {
            float2 f = as_f2(acc[m * 4 + p]);
            o[2 * p]     = f.x + bias[2 * p];
            o[2 * p + 1] = f.y + bias[2 * p + 1];
        }
        float* dst = g_xproj + (size_t)(m0 + ty * 8 + m) * H_DIM + n0 + tx * 8;
        *(float4*)(dst)     = make_float4(o[0], o[1], o[2], o[3]);
        *(float4*)(dst + 4) = make_float4(o[4], o[5], o[6], o[7]);
    }
}

// ---------------------------------------------------------------------------
// Kernel 2: 512-step recurrence + fused log_softmax.
// 256 threads, 2 batch rows per CTA (grid 128).
// Thread t = output o: computes BOTH rows' full 256-j dot alone.
//   W_hh[o][0..192)  -> 192 registers (96 ull j-pairs)
//   W_hh[o][192..256) -> smem (16 ulonglong2/thread, lane-consecutive)
// h double-buffered, plain layout; all h loads are full-warp broadcasts.
// ONE barrier per step, zero reduction, zero partial exchange.
// ---------------------------------------------------------------------------
__global__ void __launch_bounds__(256, 1) rnn_kernel(
    const float* __restrict__ W_hh, float* __restrict__ out)
{
    extern __shared__ __align__(16) float sm[];
    ulonglong2* Wsm = (ulonglong2*)sm;   // [16][256] ulonglong2 = 64 KB
    float* hbuf = sm + 16384;            // [2 buf][2 row][256] = 1024 floats
    float* red  = hbuf + 1024;           // [256]

    const int t  = threadIdx.x;          // = output index o
    const int b0 = blockIdx.x * 2;

    const ulonglong2* wr = (const ulonglong2*)(W_hh + (size_t)t * H_DIM);

    // j in [0,192): 48 ulonglong2 -> 96 ull register pairs (192 GPRs)
    ull Wp[96];
#pragma unroll
    for (int c = 0; c < 48; c++) {
        ulonglong2 v = wr[c];
        Wp[2 * c] = v.x; Wp[2 * c + 1] = v.y;
    }
    // j in [192,256): 16 ulonglong2 -> smem, lane-consecutive layout
#pragma unroll
    for (int c = 0; c < 16; c++) Wsm[c * 256 + t] = wr[48 + c];

    hbuf[t] = 0.0f;          // buf0 row A
    hbuf[256 + t] = 0.0f;    // buf0 row B
    __syncthreads();

    const float* xpA = g_xproj + (size_t)b0 * H_DIM + t;
    const float* xpB = xpA + H_DIM;
    float xvA = xpA[0];
    float xvB = xpB[0];

    for (int s = 0; s < S_LEN; s++) {
        float xnA = 0.0f, xnB = 0.0f;
        if (s + 1 < S_LEN) {
            size_t off = (size_t)(s + 1) * (B_SZ * H_DIM);
            xnA = xpA[off];
            xnB = xpB[off];
        }

        const ulonglong2* hA = (const ulonglong2*)(hbuf + (s & 1) * 512);
        const ulonglong2* hB = (const ulonglong2*)(hbuf + (s & 1) * 512 + 256);

        ull a0 = 0ULL, a1 = 0ULL, a2 = 0ULL, a3 = 0ULL;

        // j in [0,192): W from registers; h chunks are warp-uniform broadcasts
#pragma unroll
        for (int c = 0; c < 48; c++) {
            ulonglong2 ha = hA[c];
            ulonglong2 hb = hB[c];
            ffma2(a0, Wp[2 * c],     ha.x);
            ffma2(a1, Wp[2 * c + 1], ha.y);
            ffma2(a2, Wp[2 * c],     hb.x);
            ffma2(a3, Wp[2 * c + 1], hb.y);
        }
        // j in [192,256): W from smem (distinct, conflict-free)
#pragma unroll
        for (int c = 0; c < 16; c++) {
            ulonglong2 wv = Wsm[c * 256 + t];
            ulonglong2 ha = hA[48 + c];
            ulonglong2 hb = hB[48 + c];
            ffma2(a0, wv.x, ha.x);
            ffma2(a1, wv.y, ha.y);
            ffma2(a2, wv.x, hb.x);
            ffma2(a3, wv.y, hb.y);
        }

        float2 f0 = as_f2(a0), f1 = as_f2(a1), f2 = as_f2(a2), f3 = as_f2(a3);
        float hnA = tanhf(xvA + ((f0.x + f0.y) + (f1.x + f1.y)));
        float hnB = tanhf(xvB + ((f2.x + f2.y) + (f3.x + f3.y)));

        float* hn = hbuf + ((s + 1) & 1) * 512;
        hn[t]       = hnA;     // lane-consecutive STS
        hn[256 + t] = hnB;
        __syncthreads();       // single barrier per step

        xvA = xnA;
        xvB = xnB;
    }

    // Final h in buffer 0 (S_LEN even). Fused log_softmax per row.
    for (int r = 0; r < 2; r++) {
        float x = hbuf[r * 256 + t];

        red[t] = x;
        __syncthreads();
        for (int off = 128; off > 0; off >>= 1) {
            if (t < off) red[t] = fmaxf(red[t], red[t + off]);
            __syncthreads();
        }
        float mx = red[0];
        __syncthreads();

        red[t] = expf(x - mx);
        __syncthreads();
        for (int off = 128; off > 0; off >>= 1) {
            if (t < off) red[t] = red[t] + red[t + off];
            __syncthreads();
        }
        float lse = logf(red[0]);
        __syncthreads();

        out[(size_t)(b0 + r) * H_DIM + t] = x - mx - lse;
    }
}

extern "C" void kernel_launch(void* const* d_in, const int* in_sizes, int n_in,
                              void* d_out, int out_size)
{
    const int*   X    = (const int*)d_in[0];
    const float* emb  = (const float*)d_in[1];
    const float* W_ih = (const float*)d_in[2];
    const float* W_hh = (const float*)d_in[3];
    const float* b_ih = (const float*)d_in[4];
    const float* b_hh = (const float*)d_in[5];
    float* out = (float*)d_out;

    const int smem_xproj = (128 * 128 * 2) * 4 + 128 * 4;     // 131584 B
    const int smem_rnn   = 16384 * 4 + (1024 + 256) * 4;      // 70656 B
    cudaFuncSetAttribute(xproj_kernel, cudaFuncAttributeMaxDynamicSharedMemorySize, smem_xproj);
    cudaFuncSetAttribute(rnn_kernel,   cudaFuncAttributeMaxDynamicSharedMemorySize, smem_rnn);

    dim3 xgrid((S_LEN * B_SZ) / 128, 2);
    xproj_kernel<<<xgrid, 256, smem_xproj>>>(X, emb, W_ih, b_ih, b_hh);
    rnn_kernel<<<B_SZ / 2, 256, smem_rnn>>>(W_hh, out);
}